// round 8
// baseline (speedup 1.0000x reference)
#include <cuda_runtime.h>
#include <math.h>

// ---------------------------------------------------------------------------
// WriteAngleParameters: triplet gather + MLP via tf32 mma.sync (m16n8k8).
// TILE=128 triplets, 128 threads = 4 warps; warp = 32 rows x 64 cols
// (2 m-tiles x 8 n-tiles, 64 fp32 acc regs). 2 CTAs/SM.
// Layer-0: 48-stage (16-k) 3-deep cp.async pipeline for gathered x + W0.
// Weights pre-converted to tf32 (cvt.rna) once per launch into __device__ buf.
// ---------------------------------------------------------------------------

namespace {

constexpr int REP      = 256;
constexpr int BW       = 64;
constexpr int TILE     = 128;
constexpr int NTHREADS = 128;
constexpr int NSTAGE   = 48;     // 768 / 16
constexpr int SK       = 16;     // k per stage
constexpr int XS       = 20;     // x-stage row stride (floats)
constexpr int WSS      = 72;     // W row stride (floats)
constexpr int ZS       = 68;     // z row stride (floats)

constexpr float PI_F   = 3.14159265358979323846f;
constexpr float EQ_STD = 0.1f;
constexpr float K_MEAN = 120.0f;
constexpr float K_STD  = 50.0f;

// smem (floats). Phase A (layer 0): XP = 3 x 128*20 @0, WP = 3 x 16*72 @7680.
// Phase B overlay: z0 @0 (8704), z1 @8704 (8704), 2 W slots @17408 (2 x 4608).
constexpr int OFF_XP   = 0;
constexpr int XPSZ     = TILE * XS;          // 2560
constexpr int OFF_WP   = 3 * XPSZ;           // 7680
constexpr int WPSZ     = SK * WSS;           // 1152
constexpr int OFF_Z0   = 0;
constexpr int OFF_Z1   = 8704;
constexpr int OFF_SL   = 17408;              // slotA; slotB at +SLSZ
constexpr int SLSZ     = BW * WSS;           // 4608
constexpr int OFF_W4   = OFF_SL + 2 * SLSZ;  // 26624 (128 floats)
constexpr int OFF_B0   = OFF_W4 + 128;
constexpr int OFF_B1   = OFF_B0 + 64;
constexpr int OFF_BSC  = OFF_B1 + 64;        // bs + b2
constexpr int OFF_B3   = OFF_BSC + 64;
constexpr int OFF_B4   = OFF_B3 + 64;        // 4
constexpr int SMEM_FLOATS = OFF_B4 + 4;      // 27012
constexpr size_t SMEM_BYTES = (size_t)SMEM_FLOATS * sizeof(float);  // ~105.5 KB

// pre-converted tf32 weights: W0 | W1 | Ws | W2 | W3 (all k-major [fan_in][64])
constexpr int GW_W0 = 0;
constexpr int GW_W1 = 49152;
constexpr int GW_WS = 53248;
constexpr int GW_W2 = 57344;
constexpr int GW_W3 = 61440;
constexpr int GW_TOTAL = 65536;

__device__ float g_wc[GW_TOTAL];

__device__ __forceinline__ unsigned cvt_tf32(float f) {
    unsigned u;
    asm("cvt.rna.tf32.f32 %0, %1;" : "=r"(u) : "f"(f));
    return u;
}

__device__ __forceinline__ void hmma(float* d, unsigned a0, unsigned a1,
                                     unsigned a2, unsigned a3,
                                     unsigned b0, unsigned b1) {
    asm("mma.sync.aligned.m16n8k8.row.col.f32.tf32.tf32.f32 "
        "{%0,%1,%2,%3}, {%4,%5,%6,%7}, {%8,%9}, {%0,%1,%2,%3};"
        : "+f"(d[0]), "+f"(d[1]), "+f"(d[2]), "+f"(d[3])
        : "r"(a0), "r"(a1), "r"(a2), "r"(a3), "r"(b0), "r"(b1));
}

__device__ __forceinline__ void cp16(float* dst_smem, const float* src) {
    unsigned sdst = (unsigned)__cvta_generic_to_shared(dst_smem);
    asm volatile("cp.async.cg.shared.global [%0], [%1], 16;" :: "r"(sdst), "l"(src));
}
__device__ __forceinline__ void cp_commit() {
    asm volatile("cp.async.commit_group;" ::: "memory");
}
__device__ __forceinline__ void cp_wait1() {
    asm volatile("cp.async.wait_group 1;" ::: "memory");
}
__device__ __forceinline__ void cp_wait0() {
    asm volatile("cp.async.wait_group 0;" ::: "memory");
}

__device__ __forceinline__ float eluf(float x) {
    return x > 0.0f ? x : expm1f(x);
}

// One k8 step. A rows wm..wm+31 from xb (stride STRIDE), B from wb (stride WSS).
// kk = k8*8 + qt.
template<bool CVT, int STRIDE>
__device__ __forceinline__ void mm_k8(const float* __restrict__ xb,
                                      const float* __restrict__ wb,
                                      int kk, float acc[2][8][4],
                                      int wm, int qid, int qt) {
    unsigned a[2][4];
    #pragma unroll
    for (int m = 0; m < 2; m++) {
        const float* p = xb + (wm + m * 16 + qid) * STRIDE + kk;
        float f0 = p[0];
        float f1 = p[8 * STRIDE];
        float f2 = p[4];
        float f3 = p[8 * STRIDE + 4];
        if (CVT) {
            a[m][0] = cvt_tf32(f0); a[m][1] = cvt_tf32(f1);
            a[m][2] = cvt_tf32(f2); a[m][3] = cvt_tf32(f3);
        } else {
            a[m][0] = __float_as_uint(f0); a[m][1] = __float_as_uint(f1);
            a[m][2] = __float_as_uint(f2); a[m][3] = __float_as_uint(f3);
        }
    }
    #pragma unroll
    for (int t = 0; t < 8; t++) {
        unsigned b0 = __float_as_uint(wb[kk * WSS + t * 8 + qid]);
        unsigned b1 = __float_as_uint(wb[(kk + 4) * WSS + t * 8 + qid]);
        hmma(acc[0][t], a[0][0], a[0][1], a[0][2], a[0][3], b0, b1);
        hmma(acc[1][t], a[1][0], a[1][1], a[1][2], a[1][3], b0, b1);
    }
}

__device__ __forceinline__ void bias_init(const float* sb, int qt,
                                          float acc[2][8][4]) {
    #pragma unroll
    for (int t = 0; t < 8; t++) {
        float2 b = *(const float2*)(sb + t * 8 + qt * 2);
        acc[0][t][0] = b.x; acc[0][t][1] = b.y; acc[0][t][2] = b.x; acc[0][t][3] = b.y;
        acc[1][t][0] = b.x; acc[1][t][1] = b.y; acc[1][t][2] = b.x; acc[1][t][3] = b.y;
    }
}

template<bool CVT>
__device__ __forceinline__ void z_store(float* z, const float acc[2][8][4],
                                        int wm, int qid, int qt) {
    #pragma unroll
    for (int m = 0; m < 2; m++) {
        int r0 = wm + m * 16 + qid;
        #pragma unroll
        for (int t = 0; t < 8; t++) {
            float2 lo = make_float2(eluf(acc[m][t][0]), eluf(acc[m][t][1]));
            float2 hi = make_float2(eluf(acc[m][t][2]), eluf(acc[m][t][3]));
            if (CVT) {
                lo.x = __uint_as_float(cvt_tf32(lo.x));
                lo.y = __uint_as_float(cvt_tf32(lo.y));
                hi.x = __uint_as_float(cvt_tf32(hi.x));
                hi.y = __uint_as_float(cvt_tf32(hi.y));
            }
            int c = t * 8 + qt * 2;
            *(float2*)(z + r0 * ZS + c)       = lo;
            *(float2*)(z + (r0 + 8) * ZS + c) = hi;
        }
    }
}

// -------- weight tf32 pre-conversion --------
__global__ void wcvt_kernel(const float* __restrict__ W0, const float* __restrict__ W1,
                            const float* __restrict__ Ws, const float* __restrict__ W2,
                            const float* __restrict__ W3) {
    int i = blockIdx.x * 256 + threadIdx.x;
    if (i >= GW_TOTAL) return;
    float v;
    if (i < GW_W1)      v = W0[i];
    else if (i < GW_W2) v = (i < GW_WS) ? W1[i - GW_W1] : Ws[i - GW_WS];
    else                v = (i < GW_W3) ? W2[i - GW_W2] : W3[i - GW_W3];
    g_wc[i] = __uint_as_float(cvt_tf32(v));
}

// -------- main kernel --------
__global__ void __launch_bounds__(NTHREADS, 2)
wap_kernel(const float* __restrict__ h,  const int* __restrict__ idxs,
           const float* __restrict__ b0, const float* __restrict__ bs,
           const float* __restrict__ b1, const float* __restrict__ b2,
           const float* __restrict__ b3,
           const float* __restrict__ W4, const float* __restrict__ b4,
           float* __restrict__ out, int nT)
{
    extern __shared__ float smem[];
    float* sZ0   = smem + OFF_Z0;
    float* sZ1   = smem + OFF_Z1;
    float* slotA = smem + OFF_SL;
    float* slotB = smem + OFF_SL + SLSZ;
    float* sW4   = smem + OFF_W4;
    float* sb0   = smem + OFF_B0;
    float* sb1   = smem + OFF_B1;
    float* sbsc  = smem + OFF_BSC;
    float* sb3   = smem + OFF_B3;
    float* sb4   = smem + OFF_B4;

    const int tid  = threadIdx.x;
    const int lane = tid & 31;
    const int qid  = lane >> 2;       // 0..7
    const int qt   = lane & 3;        // 0..3
    const int wm   = (tid >> 5) * 32; // warp row base
    const int t0   = blockIdx.x * TILE;

    // W0 pipeline staging role: 128 threads cover 16 rows x 64 cols per stage.
    const int wrow = tid >> 3;        // 0..15
    const int wcol = (tid & 7) * 8;   // 8 floats = 2 cp16

    // ---- biases / W4 ----
    sW4[tid] = W4[tid];
    if (tid < 64) {
        sb0[tid] = b0[tid]; sb1[tid] = b1[tid];
        sbsc[tid] = bs[tid] + b2[tid]; sb3[tid] = b3[tid];
    }
    if (tid < 2) sb4[tid] = b4[tid];

    // ---- gather pointers: thread tid stages triplet row tid ----
    int t_my = t0 + tid;
    if (t_my >= nT) t_my = nT - 1;    // clamp tail (extras computed, not stored)
    const float* xsrc[3];
    xsrc[0] = h + (size_t)idxs[3 * t_my + 0] * REP;
    xsrc[1] = h + (size_t)idxs[3 * t_my + 1] * REP;
    xsrc[2] = h + (size_t)idxs[3 * t_my + 2] * REP;

    // ---- prologue: issue stages 0 and 1 ----
    #pragma unroll
    for (int s = 0; s < 2; s++) {
        const float* xs = xsrc[0] + s * SK;       // stages 0,1 are within node 0
        float* xd = smem + OFF_XP + s * XPSZ + tid * XS;
        #pragma unroll
        for (int j = 0; j < 4; j++) cp16(xd + 4 * j, xs + 4 * j);
        const float* ws = g_wc + GW_W0 + (size_t)(s * SK + wrow) * BW + wcol;
        float* wd = smem + OFF_WP + s * WPSZ + wrow * WSS + wcol;
        cp16(wd, ws); cp16(wd + 4, ws + 4);
        cp_commit();
    }
    __syncthreads();                               // biases visible

    // ---- layer 0: 48 stages x 2 k8 ----
    float acc[2][8][4];
    bias_init(sb0, qt, acc);

    for (int s = 0; s < NSTAGE; s++) {
        if (s < NSTAGE - 2) cp_wait1(); else cp_wait0();
        __syncthreads();                           // mm(s-1) done; stage s visible
        if (s + 2 < NSTAGE) {
            const int s2 = s + 2;
            const float* xs = xsrc[s2 >> 4] + (s2 & 15) * SK;
            float* xd = smem + OFF_XP + (s2 % 3) * XPSZ + tid * XS;
            #pragma unroll
            for (int j = 0; j < 4; j++) cp16(xd + 4 * j, xs + 4 * j);
            const float* ws = g_wc + GW_W0 + (size_t)(s2 * SK + wrow) * BW + wcol;
            float* wd = smem + OFF_WP + (s2 % 3) * WPSZ + wrow * WSS + wcol;
            cp16(wd, ws); cp16(wd + 4, ws + 4);
            cp_commit();
        }
        const float* xb = smem + OFF_XP + (s % 3) * XPSZ;
        const float* wb = smem + OFF_WP + (s % 3) * WPSZ;
        mm_k8<true, XS>(xb, wb, 0 + qt, acc, wm, qid, qt);
        mm_k8<true, XS>(xb, wb, 8 + qt, acc, wm, qid, qt);
    }
    __syncthreads();                               // all stage reads done: overlay ok
    z_store<true>(sZ0, acc, wm, qid, qt);

    // ---- stage W1 -> slotA, Ws -> slotB (32 floats/thread each) ----
    {
        int row = tid >> 1, part = (tid & 1) * 32;
        const float* s1 = g_wc + GW_W1 + row * BW + part;
        const float* s2 = g_wc + GW_WS + row * BW + part;
        float* d1 = slotA + row * WSS + part;
        float* d2 = slotB + row * WSS + part;
        #pragma unroll
        for (int j = 0; j < 8; j++) { cp16(d1 + 4 * j, s1 + 4 * j); cp16(d2 + 4 * j, s2 + 4 * j); }
        cp_commit(); cp_wait0();
    }
    __syncthreads();                               // z0 + W1 + Ws visible

    // ---- layer 1: z1 = elu(z0 @ W1 + b1) -> Z1 (rows warp-local) ----
    bias_init(sb1, qt, acc);
    #pragma unroll
    for (int k8 = 0; k8 < 8; k8++)
        mm_k8<false, ZS>(sZ0, slotA, k8 * 8 + qt, acc, wm, qid, qt);
    z_store<true>(sZ1, acc, wm, qid, qt);
    __syncthreads();                               // W1 reads done -> slotA reusable

    {   // prefetch W2 -> slotA under the Ws mm
        int row = tid >> 1, part = (tid & 1) * 32;
        const float* s2 = g_wc + GW_W2 + row * BW + part;
        float* d2 = slotA + row * WSS + part;
        #pragma unroll
        for (int j = 0; j < 8; j++) cp16(d2 + 4 * j, s2 + 4 * j);
        cp_commit();
    }

    // ---- residual A: acc = z0 @ Ws + (bs+b2) ----
    bias_init(sbsc, qt, acc);
    #pragma unroll
    for (int k8 = 0; k8 < 8; k8++)
        mm_k8<false, ZS>(sZ0, slotB, k8 * 8 + qt, acc, wm, qid, qt);
    cp_wait0();
    __syncthreads();                               // W2 staged; Ws reads done

    {   // prefetch W3 -> slotB under the W2 mm
        int row = tid >> 1, part = (tid & 1) * 32;
        const float* s3 = g_wc + GW_W3 + row * BW + part;
        float* d3 = slotB + row * WSS + part;
        #pragma unroll
        for (int j = 0; j < 8; j++) cp16(d3 + 4 * j, s3 + 4 * j);
        cp_commit();
    }

    // ---- residual B: acc += z1 @ W2 ; z2 = elu(acc) -> Z0 (own rows) ----
    #pragma unroll
    for (int k8 = 0; k8 < 8; k8++)
        mm_k8<false, ZS>(sZ1, slotA, k8 * 8 + qt, acc, wm, qid, qt);
    z_store<true>(sZ0, acc, wm, qid, qt);
    cp_wait0();
    __syncthreads();                               // W3 staged + visible

    // ---- layer 3: z3 = elu(z2 @ W3 + b3) -> Z1 (fp32 out, feeds head) ----
    bias_init(sb3, qt, acc);
    #pragma unroll
    for (int k8 = 0; k8 < 8; k8++)
        mm_k8<false, ZS>(sZ0, slotB, k8 * 8 + qt, acc, wm, qid, qt);
    z_store<false>(sZ1, acc, wm, qid, qt);
    __syncthreads();                               // head reads cross-warp

    // ---- head: one triplet per thread (fp32) ----
    {
        int t = t0 + tid;
        if (t < nT) {
            const float* zrow = sZ1 + tid * ZS;
            float c0 = sb4[0], c1 = sb4[1];
            #pragma unroll
            for (int k4 = 0; k4 < 16; k4++) {
                float4 z4 = *(const float4*)(zrow + k4 * 4);
                float4 wA = *(const float4*)(sW4 + k4 * 8);
                float4 wB = *(const float4*)(sW4 + k4 * 8 + 4);
                c0 += z4.x * wA.x + z4.y * wA.z + z4.z * wB.x + z4.w * wB.z;
                c1 += z4.x * wA.y + z4.y * wA.w + z4.z * wB.y + z4.w * wB.w;
            }
            float eq = PI_F / (1.0f + expf(-c0 * (EQ_STD / PI_F)));
            float kk = K_STD * eluf(c1 + K_MEAN / K_STD);
            *(float2*)(out + (size_t)t * 2) = make_float2(eq, kk);
        }
    }
}

} // namespace

extern "C" void kernel_launch(void* const* d_in, const int* in_sizes, int n_in,
                              void* d_out, int out_size) {
    const float* h   = (const float*)d_in[0];
    const int*   idx = (const int*)  d_in[1];
    const float* W0  = (const float*)d_in[2];
    const float* b0  = (const float*)d_in[3];
    const float* Ws  = (const float*)d_in[4];
    const float* bs  = (const float*)d_in[5];
    const float* W1  = (const float*)d_in[6];
    const float* b1  = (const float*)d_in[7];
    const float* W2  = (const float*)d_in[8];
    const float* b2  = (const float*)d_in[9];
    const float* W3  = (const float*)d_in[10];
    const float* b3  = (const float*)d_in[11];
    const float* W4  = (const float*)d_in[12];
    const float* b4  = (const float*)d_in[13];
    float* out = (float*)d_out;

    int nT = in_sizes[1] / 3;
    int grid = (nT + TILE - 1) / TILE;

    wcvt_kernel<<<(GW_TOTAL + 255) / 256, 256>>>(W0, W1, Ws, W2, W3);

    cudaFuncSetAttribute(wap_kernel,
                         cudaFuncAttributeMaxDynamicSharedMemorySize,
                         (int)SMEM_BYTES);
    wap_kernel<<<grid, NTHREADS, SMEM_BYTES>>>(
        h, idx, b0, bs, b1, b2, b3, W4, b4, out, nT);
    (void)n_in; (void)out_size;
}

// round 12
// speedup vs baseline: 2.0669x; 2.0669x over previous
#include <cuda_runtime.h>
#include <math.h>

// ---------------------------------------------------------------------------
// WriteAngleParameters: triplet gather + MLP via tf32 mma.sync (m16n8k8).
// TILE=128 triplets, 256 threads = 8 warps; warp = 16 rows x 64 cols
// (1 m-tile x 8 n-tiles, 32 fp32 acc regs). 2 CTAs/SM.
// Layer-0: 24-stage (32-k) 4-deep cp.async pipeline for gathered x + W0.
// Weights pre-converted to tf32 (cvt.rna) once per launch into __device__ buf.
// ---------------------------------------------------------------------------

namespace {

constexpr int REP      = 256;
constexpr int BW       = 64;
constexpr int TILE     = 128;
constexpr int NTHREADS = 256;
constexpr int SK       = 32;     // k per stage
constexpr int NSTAGE   = 24;     // 768 / 32
constexpr int XS       = 36;     // x-stage row stride (floats)
constexpr int WSS      = 72;     // W row stride (floats)
constexpr int ZS       = 68;     // z row stride (floats)

constexpr float PI_F   = 3.14159265358979323846f;
constexpr float EQ_STD = 0.1f;
constexpr float K_MEAN = 120.0f;
constexpr float K_STD  = 50.0f;

// smem (floats). Phase A (layer 0): XP = 4 x 128*36 @0, WP = 4 x 32*72 @18432.
// Phase B overlay: z0 @0 (8704), z1 @8704, 2 W slots @17408 (2 x 4608 = 9216).
constexpr int OFF_XP   = 0;
constexpr int XPSZ     = TILE * XS;          // 4608
constexpr int OFF_WP   = 4 * XPSZ;           // 18432
constexpr int WPSZ     = SK * WSS;           // 2304
constexpr int PHA_END  = OFF_WP + 4 * WPSZ;  // 27648
constexpr int OFF_Z0   = 0;
constexpr int OFF_Z1   = 8704;
constexpr int OFF_SL   = 17408;              // slotA; slotB at +SLSZ
constexpr int SLSZ     = BW * WSS;           // 4608
constexpr int OFF_W4   = PHA_END;            // 128 floats
constexpr int OFF_B0   = OFF_W4 + 128;
constexpr int OFF_B1   = OFF_B0 + 64;
constexpr int OFF_BSC  = OFF_B1 + 64;        // bs + b2
constexpr int OFF_B3   = OFF_BSC + 64;
constexpr int OFF_B4   = OFF_B3 + 64;        // 4
constexpr int SMEM_FLOATS = OFF_B4 + 4;      // 28036
constexpr size_t SMEM_BYTES = (size_t)SMEM_FLOATS * sizeof(float);  // 112144 B

// pre-converted tf32 weights: W0 | W1 | Ws | W2 | W3 (all k-major [fan_in][64])
constexpr int GW_W0 = 0;
constexpr int GW_W1 = 49152;
constexpr int GW_WS = 53248;
constexpr int GW_W2 = 57344;
constexpr int GW_W3 = 61440;
constexpr int GW_TOTAL = 65536;

__device__ float g_wc[GW_TOTAL];

__device__ __forceinline__ unsigned cvt_tf32(float f) {
    unsigned u;
    asm("cvt.rna.tf32.f32 %0, %1;" : "=r"(u) : "f"(f));
    return u;
}

__device__ __forceinline__ void hmma(float* d, unsigned a0, unsigned a1,
                                     unsigned a2, unsigned a3,
                                     unsigned b0, unsigned b1) {
    asm("mma.sync.aligned.m16n8k8.row.col.f32.tf32.tf32.f32 "
        "{%0,%1,%2,%3}, {%4,%5,%6,%7}, {%8,%9}, {%0,%1,%2,%3};"
        : "+f"(d[0]), "+f"(d[1]), "+f"(d[2]), "+f"(d[3])
        : "r"(a0), "r"(a1), "r"(a2), "r"(a3), "r"(b0), "r"(b1));
}

__device__ __forceinline__ void cp16(float* dst_smem, const float* src) {
    unsigned sdst = (unsigned)__cvta_generic_to_shared(dst_smem);
    asm volatile("cp.async.cg.shared.global [%0], [%1], 16;" :: "r"(sdst), "l"(src));
}
__device__ __forceinline__ void cp_commit() {
    asm volatile("cp.async.commit_group;" ::: "memory");
}
template<int N>
__device__ __forceinline__ void cp_wait() {
    asm volatile("cp.async.wait_group %0;" :: "n"(N) : "memory");
}

__device__ __forceinline__ float eluf(float x) {
    return x > 0.0f ? x : expm1f(x);
}

// One k8 step for a 16-row warp tile. A rows wm..wm+15 from xb (stride STRIDE),
// B (8 n-tiles) from wb (stride WSS). kk = k8*8 + qt.
template<bool CVT, int STRIDE>
__device__ __forceinline__ void mm_k8(const float* __restrict__ xb,
                                      const float* __restrict__ wb,
                                      int kk, float acc[8][4],
                                      int wm, int qid, int qt) {
    const float* p = xb + (wm + qid) * STRIDE + kk;
    float f0 = p[0];
    float f1 = p[8 * STRIDE];
    float f2 = p[4];
    float f3 = p[8 * STRIDE + 4];
    unsigned a0, a1, a2, a3;
    if (CVT) {
        a0 = cvt_tf32(f0); a1 = cvt_tf32(f1); a2 = cvt_tf32(f2); a3 = cvt_tf32(f3);
    } else {
        a0 = __float_as_uint(f0); a1 = __float_as_uint(f1);
        a2 = __float_as_uint(f2); a3 = __float_as_uint(f3);
    }
    #pragma unroll
    for (int t = 0; t < 8; t++) {
        unsigned b0 = __float_as_uint(wb[kk * WSS + t * 8 + qid]);
        unsigned b1 = __float_as_uint(wb[(kk + 4) * WSS + t * 8 + qid]);
        hmma(acc[t], a0, a1, a2, a3, b0, b1);
    }
}

__device__ __forceinline__ void bias_init(const float* sb, int qt, float acc[8][4]) {
    #pragma unroll
    for (int t = 0; t < 8; t++) {
        float2 b = *(const float2*)(sb + t * 8 + qt * 2);
        acc[t][0] = b.x; acc[t][1] = b.y; acc[t][2] = b.x; acc[t][3] = b.y;
    }
}

template<bool CVT>
__device__ __forceinline__ void z_store(float* z, const float acc[8][4],
                                        int wm, int qid, int qt) {
    int r0 = wm + qid;
    #pragma unroll
    for (int t = 0; t < 8; t++) {
        float2 lo = make_float2(eluf(acc[t][0]), eluf(acc[t][1]));
        float2 hi = make_float2(eluf(acc[t][2]), eluf(acc[t][3]));
        if (CVT) {
            lo.x = __uint_as_float(cvt_tf32(lo.x));
            lo.y = __uint_as_float(cvt_tf32(lo.y));
            hi.x = __uint_as_float(cvt_tf32(hi.x));
            hi.y = __uint_as_float(cvt_tf32(hi.y));
        }
        int c = t * 8 + qt * 2;
        *(float2*)(z + r0 * ZS + c)       = lo;
        *(float2*)(z + (r0 + 8) * ZS + c) = hi;
    }
}

// -------- weight tf32 pre-conversion --------
__global__ void wcvt_kernel(const float* __restrict__ W0, const float* __restrict__ W1,
                            const float* __restrict__ Ws, const float* __restrict__ W2,
                            const float* __restrict__ W3) {
    int i = blockIdx.x * 256 + threadIdx.x;
    if (i >= GW_TOTAL) return;
    float v;
    if (i < GW_W1)      v = W0[i];
    else if (i < GW_W2) v = (i < GW_WS) ? W1[i - GW_W1] : Ws[i - GW_WS];
    else                v = (i < GW_W3) ? W2[i - GW_W2] : W3[i - GW_W3];
    g_wc[i] = __uint_as_float(cvt_tf32(v));
}

// -------- main kernel --------
__global__ void __launch_bounds__(NTHREADS, 2)
wap_kernel(const float* __restrict__ h,  const int* __restrict__ idxs,
           const float* __restrict__ b0, const float* __restrict__ bs,
           const float* __restrict__ b1, const float* __restrict__ b2,
           const float* __restrict__ b3,
           const float* __restrict__ W4, const float* __restrict__ b4,
           float* __restrict__ out, int nT)
{
    extern __shared__ float smem[];
    float* sZ0   = smem + OFF_Z0;
    float* sZ1   = smem + OFF_Z1;
    float* slotA = smem + OFF_SL;
    float* slotB = smem + OFF_SL + SLSZ;
    float* sW4   = smem + OFF_W4;
    float* sb0   = smem + OFF_B0;
    float* sb1   = smem + OFF_B1;
    float* sbsc  = smem + OFF_BSC;
    float* sb3   = smem + OFF_B3;
    float* sb4   = smem + OFF_B4;

    const int tid  = threadIdx.x;
    const int lane = tid & 31;
    const int qid  = lane >> 2;       // 0..7
    const int qt   = lane & 3;        // 0..3
    const int wm   = (tid >> 5) * 16; // warp row base (8 warps x 16 rows)
    const int t0   = blockIdx.x * TILE;

    // staging roles
    const int xrow  = tid >> 1;           // 0..127 (x: 2 threads per row)
    const int xhalf = (tid & 1) * 16;     // 16 floats each
    const int wrow  = tid >> 3;           // 0..31  (W0: 32 rows x 64 cols/stage)
    const int wcol  = (tid & 7) * 8;      // 8 floats = 2 cp16
    const int srow  = tid >> 2;           // 0..63  (slots: 64 rows)
    const int scol  = (tid & 3) * 16;     // 16 floats = 4 cp16

    // ---- biases / W4 ----
    if (tid < 128) sW4[tid] = W4[tid];
    if (tid < 64) {
        sb0[tid] = b0[tid]; sb1[tid] = b1[tid];
        sbsc[tid] = bs[tid] + b2[tid]; sb3[tid] = b3[tid];
    }
    if (tid < 2) sb4[tid] = b4[tid];

    // ---- gather pointers for my staging row ----
    int t_my = t0 + xrow;
    if (t_my >= nT) t_my = nT - 1;    // clamp tail (extras computed, not stored)
    const float* xsrc[3];
    xsrc[0] = h + (size_t)idxs[3 * t_my + 0] * REP;
    xsrc[1] = h + (size_t)idxs[3 * t_my + 1] * REP;
    xsrc[2] = h + (size_t)idxs[3 * t_my + 2] * REP;

    // ---- prologue: issue stages 0,1,2 (all within node 0: 8 stages/node) ----
    #pragma unroll
    for (int s = 0; s < 3; s++) {
        const float* xs = xsrc[0] + s * SK + xhalf;
        float* xd = smem + OFF_XP + s * XPSZ + xrow * XS + xhalf;
        #pragma unroll
        for (int j = 0; j < 4; j++) cp16(xd + 4 * j, xs + 4 * j);
        const float* ws = g_wc + GW_W0 + (size_t)(s * SK + wrow) * BW + wcol;
        float* wd = smem + OFF_WP + s * WPSZ + wrow * WSS + wcol;
        cp16(wd, ws); cp16(wd + 4, ws + 4);
        cp_commit();
    }
    __syncthreads();                               // biases visible

    // ---- layer 0: 24 stages x 4 k8 ----
    float acc[8][4];
    bias_init(sb0, qt, acc);

    for (int s = 0; s < NSTAGE; s++) {
        if (s < NSTAGE - 3)      cp_wait<3>();
        else if (s < NSTAGE - 2) cp_wait<2>();
        else if (s < NSTAGE - 1) cp_wait<1>();
        else                     cp_wait<0>();
        __syncthreads();                           // mm(s-1) done; stage s visible
        if (s + 3 < NSTAGE) {
            const int s2 = s + 3;
            const float* xs = xsrc[s2 >> 3] + (s2 & 7) * SK + xhalf;
            float* xd = smem + OFF_XP + (s2 & 3) * XPSZ + xrow * XS + xhalf;
            #pragma unroll
            for (int j = 0; j < 4; j++) cp16(xd + 4 * j, xs + 4 * j);
            const float* ws = g_wc + GW_W0 + (size_t)(s2 * SK + wrow) * BW + wcol;
            float* wd = smem + OFF_WP + (s2 & 3) * WPSZ + wrow * WSS + wcol;
            cp16(wd, ws); cp16(wd + 4, ws + 4);
            cp_commit();
        }
        const float* xb = smem + OFF_XP + (s & 3) * XPSZ;
        const float* wb = smem + OFF_WP + (s & 3) * WPSZ;
        #pragma unroll
        for (int k8 = 0; k8 < 4; k8++)
            mm_k8<true, XS>(xb, wb, k8 * 8 + qt, acc, wm, qid, qt);
    }
    __syncthreads();                               // all stage reads done: overlay ok
    z_store<true>(sZ0, acc, wm, qid, qt);

    // ---- stage W1 -> slotA, Ws -> slotB (16 floats/thread each) ----
    {
        const float* s1 = g_wc + GW_W1 + srow * BW + scol;
        const float* s2 = g_wc + GW_WS + srow * BW + scol;
        float* d1 = slotA + srow * WSS + scol;
        float* d2 = slotB + srow * WSS + scol;
        #pragma unroll
        for (int j = 0; j < 4; j++) { cp16(d1 + 4 * j, s1 + 4 * j); cp16(d2 + 4 * j, s2 + 4 * j); }
        cp_commit(); cp_wait<0>();
    }
    __syncthreads();                               // z0 + W1 + Ws visible

    // ---- layer 1: z1 = elu(z0 @ W1 + b1) -> Z1 (rows warp-local) ----
    bias_init(sb1, qt, acc);
    #pragma unroll
    for (int k8 = 0; k8 < 8; k8++)
        mm_k8<false, ZS>(sZ0, slotA, k8 * 8 + qt, acc, wm, qid, qt);
    z_store<true>(sZ1, acc, wm, qid, qt);
    __syncthreads();                               // W1 reads done -> slotA reusable

    {   // prefetch W2 -> slotA under the Ws mm
        const float* s2 = g_wc + GW_W2 + srow * BW + scol;
        float* d2 = slotA + srow * WSS + scol;
        #pragma unroll
        for (int j = 0; j < 4; j++) cp16(d2 + 4 * j, s2 + 4 * j);
        cp_commit();
    }

    // ---- residual A: acc = z0 @ Ws + (bs+b2) ----
    bias_init(sbsc, qt, acc);
    #pragma unroll
    for (int k8 = 0; k8 < 8; k8++)
        mm_k8<false, ZS>(sZ0, slotB, k8 * 8 + qt, acc, wm, qid, qt);
    cp_wait<0>();
    __syncthreads();                               // W2 staged; Ws reads done

    {   // prefetch W3 -> slotB under the W2 mm
        const float* s3 = g_wc + GW_W3 + srow * BW + scol;
        float* d3 = slotB + srow * WSS + scol;
        #pragma unroll
        for (int j = 0; j < 4; j++) cp16(d3 + 4 * j, s3 + 4 * j);
        cp_commit();
    }

    // ---- residual B: acc += z1 @ W2 ; z2 = elu(acc) -> Z0 (own rows) ----
    #pragma unroll
    for (int k8 = 0; k8 < 8; k8++)
        mm_k8<false, ZS>(sZ1, slotA, k8 * 8 + qt, acc, wm, qid, qt);
    z_store<true>(sZ0, acc, wm, qid, qt);
    cp_wait<0>();
    __syncthreads();                               // W3 staged + visible

    // ---- layer 3: z3 = elu(z2 @ W3 + b3) -> Z1 (fp32 out, feeds head) ----
    bias_init(sb3, qt, acc);
    #pragma unroll
    for (int k8 = 0; k8 < 8; k8++)
        mm_k8<false, ZS>(sZ0, slotB, k8 * 8 + qt, acc, wm, qid, qt);
    z_store<false>(sZ1, acc, wm, qid, qt);
    __syncthreads();                               // head reads cross-warp

    // ---- head: threads 0..127, one triplet each (fp32) ----
    if (tid < TILE) {
        int t = t0 + tid;
        if (t < nT) {
            const float* zrow = sZ1 + tid * ZS;
            float c0 = sb4[0], c1 = sb4[1];
            #pragma unroll
            for (int k4 = 0; k4 < 16; k4++) {
                float4 z4 = *(const float4*)(zrow + k4 * 4);
                float4 wA = *(const float4*)(sW4 + k4 * 8);
                float4 wB = *(const float4*)(sW4 + k4 * 8 + 4);
                c0 += z4.x * wA.x + z4.y * wA.z + z4.z * wB.x + z4.w * wB.z;
                c1 += z4.x * wA.y + z4.y * wA.w + z4.z * wB.y + z4.w * wB.w;
            }
            float eq = PI_F / (1.0f + expf(-c0 * (EQ_STD / PI_F)));
            float kk = K_STD * eluf(c1 + K_MEAN / K_STD);
            *(float2*)(out + (size_t)t * 2) = make_float2(eq, kk);
        }
    }
}

} // namespace

extern "C" void kernel_launch(void* const* d_in, const int* in_sizes, int n_in,
                              void* d_out, int out_size) {
    const float* h   = (const float*)d_in[0];
    const int*   idx = (const int*)  d_in[1];
    const float* W0  = (const float*)d_in[2];
    const float* b0  = (const float*)d_in[3];
    const float* Ws  = (const float*)d_in[4];
    const float* bs  = (const float*)d_in[5];
    const float* W1  = (const float*)d_in[6];
    const float* b1  = (const float*)d_in[7];
    const float* W2  = (const float*)d_in[8];
    const float* b2  = (const float*)d_in[9];
    const float* W3  = (const float*)d_in[10];
    const float* b3  = (const float*)d_in[11];
    const float* W4  = (const float*)d_in[12];
    const float* b4  = (const float*)d_in[13];
    float* out = (float*)d_out;

    int nT = in_sizes[1] / 3;
    int grid = (nT + TILE - 1) / TILE;

    wcvt_kernel<<<(GW_TOTAL + 255) / 256, 256>>>(W0, W1, Ws, W2, W3);

    cudaFuncSetAttribute(wap_kernel,
                         cudaFuncAttributeMaxDynamicSharedMemorySize,
                         (int)SMEM_BYTES);
    wap_kernel<<<grid, NTHREADS, SMEM_BYTES>>>(
        h, idx, b0, bs, b1, b2, b3, W4, b4, out, nT);
    (void)n_in; (void)out_size;
}

// round 14
// speedup vs baseline: 2.1682x; 1.0490x over previous
#include <cuda_runtime.h>
#include <math.h>

// ---------------------------------------------------------------------------
// WriteAngleParameters: triplet gather + MLP via tf32 mma.sync (m16n8k8),
// fragments loaded with ldmatrix (A row-major; B via n-major weight storage).
// TILE=128 triplets, 256 threads = 8 warps; warp = 16 rows x 64 cols.
// 2 CTAs/SM. Layer-0: 24-stage (32-k) 4-deep cp.async pipeline.
// Weights pre-converted to tf32 AND transposed to n-major once per launch.
// ---------------------------------------------------------------------------

namespace {

constexpr int REP      = 256;
constexpr int BW       = 64;
constexpr int TILE     = 128;
constexpr int NTHREADS = 256;
constexpr int SK       = 32;     // k per stage
constexpr int NSTAGE   = 24;     // 768 / 32
constexpr int XS       = 36;     // x-stage row stride (floats)
constexpr int WTS      = 36;     // W0-stage n-row stride (floats), 32 k per stage
constexpr int SLS      = 68;     // slot n-row stride (floats), 64 k
constexpr int ZS       = 68;     // z row stride (floats)

constexpr float PI_F   = 3.14159265358979323846f;
constexpr float EQ_STD = 0.1f;
constexpr float K_MEAN = 120.0f;
constexpr float K_STD  = 50.0f;

// smem (floats). Phase A (layer 0): XP = 4 x 128*36 @0, WP = 4 x 64*36 @18432.
// Phase B overlay: z0 @0 (8704), z1 @8704, 2 W slots @17408 (2 x 4352).
constexpr int OFF_XP   = 0;
constexpr int XPSZ     = TILE * XS;          // 4608
constexpr int OFF_WP   = 4 * XPSZ;           // 18432
constexpr int WPSZ     = BW * WTS;           // 2304
constexpr int PHA_END  = OFF_WP + 4 * WPSZ;  // 27648
constexpr int OFF_Z0   = 0;
constexpr int OFF_Z1   = 8704;
constexpr int OFF_SL   = 17408;              // slotA; slotB at +SLSZ
constexpr int SLSZ     = BW * SLS;           // 4352
constexpr int OFF_W4   = PHA_END;            // 128 floats
constexpr int OFF_B0   = OFF_W4 + 128;
constexpr int OFF_B1   = OFF_B0 + 64;
constexpr int OFF_BSC  = OFF_B1 + 64;        // bs + b2
constexpr int OFF_B3   = OFF_BSC + 64;
constexpr int OFF_B4   = OFF_B3 + 64;        // 4
constexpr int SMEM_FLOATS = OFF_B4 + 4;
constexpr size_t SMEM_BYTES = (size_t)SMEM_FLOATS * sizeof(float);  // ~112.1 KB

// pre-converted tf32 weights, n-major: W0 [64][768] | W1|Ws|W2|W3 [64][64]
constexpr int GW_W0 = 0;
constexpr int GW_W1 = 49152;
constexpr int GW_WS = 53248;
constexpr int GW_W2 = 57344;
constexpr int GW_W3 = 61440;
constexpr int GW_TOTAL = 65536;

__device__ float g_wc[GW_TOTAL];

__device__ __forceinline__ unsigned cvt_tf32(float f) {
    unsigned u;
    asm("cvt.rna.tf32.f32 %0, %1;" : "=r"(u) : "f"(f));
    return u;
}

__device__ __forceinline__ void hmma(float* d, unsigned a0, unsigned a1,
                                     unsigned a2, unsigned a3,
                                     unsigned b0, unsigned b1) {
    asm("mma.sync.aligned.m16n8k8.row.col.f32.tf32.tf32.f32 "
        "{%0,%1,%2,%3}, {%4,%5,%6,%7}, {%8,%9}, {%0,%1,%2,%3};"
        : "+f"(d[0]), "+f"(d[1]), "+f"(d[2]), "+f"(d[3])
        : "r"(a0), "r"(a1), "r"(a2), "r"(a3), "r"(b0), "r"(b1));
}

__device__ __forceinline__ void ldsm4(unsigned& r0, unsigned& r1,
                                      unsigned& r2, unsigned& r3, unsigned addr) {
    asm volatile("ldmatrix.sync.aligned.m8n8.x4.shared.b16 {%0,%1,%2,%3}, [%4];"
                 : "=r"(r0), "=r"(r1), "=r"(r2), "=r"(r3) : "r"(addr));
}

__device__ __forceinline__ void cp16(float* dst_smem, const float* src) {
    unsigned sdst = (unsigned)__cvta_generic_to_shared(dst_smem);
    asm volatile("cp.async.cg.shared.global [%0], [%1], 16;" :: "r"(sdst), "l"(src));
}
__device__ __forceinline__ void cp_commit() {
    asm volatile("cp.async.commit_group;" ::: "memory");
}
template<int N>
__device__ __forceinline__ void cp_wait() {
    asm volatile("cp.async.wait_group %0;" :: "n"(N) : "memory");
}

__device__ __forceinline__ float eluf(float x) {
    return x > 0.0f ? x : expm1f(x);
}

// One k8 step. a_addr: per-lane A ldsm address (A rows, stride per caller).
// b_addr: per-lane B ldsm address over n-major weights (stride STB floats).
// Covers 8 n-tiles via 4 ldsm.x4 (2 tiles each).
template<bool CVT, int STB>
__device__ __forceinline__ void mm_k8_l(unsigned a_addr, unsigned b_addr,
                                        float acc[8][4]) {
    unsigned a0, a1, a2, a3;
    ldsm4(a0, a1, a2, a3, a_addr);
    if (CVT) {
        a0 = cvt_tf32(__uint_as_float(a0));
        a1 = cvt_tf32(__uint_as_float(a1));
        a2 = cvt_tf32(__uint_as_float(a2));
        a3 = cvt_tf32(__uint_as_float(a3));
    }
    #pragma unroll
    for (int t = 0; t < 4; t++) {
        unsigned b0, b1, b2, b3;
        ldsm4(b0, b1, b2, b3, b_addr + t * (16 * STB * 4));
        hmma(acc[2 * t],     a0, a1, a2, a3, b0, b1);
        hmma(acc[2 * t + 1], a0, a1, a2, a3, b2, b3);
    }
}

__device__ __forceinline__ void bias_init(const float* sb, int qt, float acc[8][4]) {
    #pragma unroll
    for (int t = 0; t < 8; t++) {
        float2 b = *(const float2*)(sb + t * 8 + qt * 2);
        acc[t][0] = b.x; acc[t][1] = b.y; acc[t][2] = b.x; acc[t][3] = b.y;
    }
}

template<bool CVT>
__device__ __forceinline__ void z_store(float* z, const float acc[8][4],
                                        int wm, int qid, int qt) {
    int r0 = wm + qid;
    #pragma unroll
    for (int t = 0; t < 8; t++) {
        float2 lo = make_float2(eluf(acc[t][0]), eluf(acc[t][1]));
        float2 hi = make_float2(eluf(acc[t][2]), eluf(acc[t][3]));
        if (CVT) {
            lo.x = __uint_as_float(cvt_tf32(lo.x));
            lo.y = __uint_as_float(cvt_tf32(lo.y));
            hi.x = __uint_as_float(cvt_tf32(hi.x));
            hi.y = __uint_as_float(cvt_tf32(hi.y));
        }
        int c = t * 8 + qt * 2;
        *(float2*)(z + r0 * ZS + c)       = lo;
        *(float2*)(z + (r0 + 8) * ZS + c) = hi;
    }
}

// -------- weight tf32 pre-conversion + transpose to n-major --------
__global__ void wcvt_kernel(const float* __restrict__ W0, const float* __restrict__ W1,
                            const float* __restrict__ Ws, const float* __restrict__ W2,
                            const float* __restrict__ W3) {
    int i = blockIdx.x * 256 + threadIdx.x;
    if (i >= GW_TOTAL) return;
    float v;
    if (i < GW_W1) {                       // W0: dst = n*768 + k
        int n = i / 768, k = i % 768;
        v = W0[k * 64 + n];
    } else {                               // small: dst = base + n*64 + k
        int j = i - GW_W1;
        int m = j >> 12;                   // 0..3 -> W1, Ws, W2, W3
        int n = (j & 4095) >> 6, k = j & 63;
        const float* src = m == 0 ? W1 : m == 1 ? Ws : m == 2 ? W2 : W3;
        v = src[k * 64 + n];
    }
    g_wc[i] = __uint_as_float(cvt_tf32(v));
}

// -------- main kernel --------
__global__ void __launch_bounds__(NTHREADS, 2)
wap_kernel(const float* __restrict__ h,  const int* __restrict__ idxs,
           const float* __restrict__ b0, const float* __restrict__ bs,
           const float* __restrict__ b1, const float* __restrict__ b2,
           const float* __restrict__ b3,
           const float* __restrict__ W4, const float* __restrict__ b4,
           float* __restrict__ out, int nT)
{
    extern __shared__ float smem[];
    float* sZ0   = smem + OFF_Z0;
    float* sZ1   = smem + OFF_Z1;
    float* slotA = smem + OFF_SL;
    float* slotB = smem + OFF_SL + SLSZ;
    float* sW4   = smem + OFF_W4;
    float* sb0   = smem + OFF_B0;
    float* sb1   = smem + OFF_B1;
    float* sbsc  = smem + OFF_BSC;
    float* sb3   = smem + OFF_B3;
    float* sb4   = smem + OFF_B4;

    const int tid  = threadIdx.x;
    const int lane = tid & 31;
    const int qid  = lane >> 2;
    const int qt   = lane & 3;
    const int wm   = (tid >> 5) * 16;     // warp row base
    const int t0   = blockIdx.x * TILE;

    const unsigned smem_u32 = (unsigned)__cvta_generic_to_shared(smem);

    // per-lane ldsm offsets (bytes)
    const int arow  = wm + (lane & 15);
    const int ksel  = (lane >> 4) & 1;           // col +4 for lanes 16-31
    const unsigned a_offX = (unsigned)((arow * XS + ksel * 4) * 4);
    const unsigned a_offZ = (unsigned)((arow * ZS + ksel * 4) * 4);
    const int brow  = (lane & 7) + ((lane >> 4) & 1) * 8;   // n within pair
    const int bksel = (lane >> 3) & 1;                       // col +4
    const unsigned b_offW = (unsigned)((brow * WTS + bksel * 4) * 4);
    const unsigned b_offS = (unsigned)((brow * SLS + bksel * 4) * 4);

    // staging roles
    const int xrow  = tid >> 1;           // 0..127
    const int xhalf = (tid & 1) * 16;
    const int wrow  = tid >> 2;           // 0..63 (n rows, both W0 stages and slots)
    const int wpart8  = (tid & 3) * 8;    // W0 stage: 8 floats
    const int wpart16 = (tid & 3) * 16;   // slots: 16 floats

    // ---- biases / W4 ----
    if (tid < 128) sW4[tid] = W4[tid];
    if (tid < 64) {
        sb0[tid] = b0[tid]; sb1[tid] = b1[tid];
        sbsc[tid] = bs[tid] + b2[tid]; sb3[tid] = b3[tid];
    }
    if (tid < 2) sb4[tid] = b4[tid];

    // ---- gather pointers for my staging row ----
    int t_my = t0 + xrow;
    if (t_my >= nT) t_my = nT - 1;        // clamp tail
    const float* xsrc[3];
    xsrc[0] = h + (size_t)idxs[3 * t_my + 0] * REP;
    xsrc[1] = h + (size_t)idxs[3 * t_my + 1] * REP;
    xsrc[2] = h + (size_t)idxs[3 * t_my + 2] * REP;

    // ---- prologue: issue stages 0,1,2 ----
    #pragma unroll
    for (int s = 0; s < 3; s++) {
        const float* xs = xsrc[0] + s * SK + xhalf;
        float* xd = smem + OFF_XP + s * XPSZ + xrow * XS + xhalf;
        #pragma unroll
        for (int j = 0; j < 4; j++) cp16(xd + 4 * j, xs + 4 * j);
        const float* ws = g_wc + GW_W0 + (size_t)wrow * 768 + s * SK + wpart8;
        float* wd = smem + OFF_WP + s * WPSZ + wrow * WTS + wpart8;
        cp16(wd, ws); cp16(wd + 4, ws + 4);
        cp_commit();
    }
    __syncthreads();                               // biases visible

    // ---- layer 0: 24 stages x 4 k8 ----
    float acc[8][4];
    bias_init(sb0, qt, acc);

    for (int s = 0; s < NSTAGE; s++) {
        if (s < NSTAGE - 3)      cp_wait<3>();
        else if (s < NSTAGE - 2) cp_wait<2>();
        else if (s < NSTAGE - 1) cp_wait<1>();
        else                     cp_wait<0>();
        __syncthreads();                           // mm(s-1) done; stage s visible
        if (s + 3 < NSTAGE) {
            const int s2 = s + 3;
            const float* xs = xsrc[s2 >> 3] + (s2 & 7) * SK + xhalf;
            float* xd = smem + OFF_XP + (s2 & 3) * XPSZ + xrow * XS + xhalf;
            #pragma unroll
            for (int j = 0; j < 4; j++) cp16(xd + 4 * j, xs + 4 * j);
            const float* ws = g_wc + GW_W0 + (size_t)wrow * 768 + s2 * SK + wpart8;
            float* wd = smem + OFF_WP + (s2 & 3) * WPSZ + wrow * WTS + wpart8;
            cp16(wd, ws); cp16(wd + 4, ws + 4);
            cp_commit();
        }
        unsigned xa = smem_u32 + (unsigned)((OFF_XP + (s & 3) * XPSZ) * 4) + a_offX;
        unsigned wa = smem_u32 + (unsigned)((OFF_WP + (s & 3) * WPSZ) * 4) + b_offW;
        #pragma unroll
        for (int k8 = 0; k8 < 4; k8++)
            mm_k8_l<true, WTS>(xa + k8 * 32, wa + k8 * 32, acc);
    }
    __syncthreads();                               // all stage reads done: overlay ok
    z_store<true>(sZ0, acc, wm, qid, qt);

    // ---- stage W1 -> slotA, Ws -> slotB (16 floats/thread each) ----
    {
        const float* s1 = g_wc + GW_W1 + wrow * BW + wpart16;
        const float* s2 = g_wc + GW_WS + wrow * BW + wpart16;
        float* d1 = slotA + wrow * SLS + wpart16;
        float* d2 = slotB + wrow * SLS + wpart16;
        #pragma unroll
        for (int j = 0; j < 4; j++) { cp16(d1 + 4 * j, s1 + 4 * j); cp16(d2 + 4 * j, s2 + 4 * j); }
        cp_commit(); cp_wait<0>();
    }
    __syncthreads();                               // z0 + W1 + Ws visible

    const unsigned z0a = smem_u32 + (unsigned)(OFF_Z0 * 4) + a_offZ;
    const unsigned z1a = smem_u32 + (unsigned)(OFF_Z1 * 4) + a_offZ;
    const unsigned slA = smem_u32 + (unsigned)(OFF_SL * 4) + b_offS;
    const unsigned slB = slA + (unsigned)(SLSZ * 4);

    // ---- layer 1: z1 = elu(z0 @ W1 + b1) -> Z1 (rows warp-local) ----
    bias_init(sb1, qt, acc);
    #pragma unroll
    for (int k8 = 0; k8 < 8; k8++)
        mm_k8_l<false, SLS>(z0a + k8 * 32, slA + k8 * 32, acc);
    z_store<true>(sZ1, acc, wm, qid, qt);
    __syncthreads();                               // W1 reads done -> slotA reusable

    {   // prefetch W2 -> slotA under the Ws mm
        const float* s2 = g_wc + GW_W2 + wrow * BW + wpart16;
        float* d2 = slotA + wrow * SLS + wpart16;
        #pragma unroll
        for (int j = 0; j < 4; j++) cp16(d2 + 4 * j, s2 + 4 * j);
        cp_commit();
    }

    // ---- residual A: acc = z0 @ Ws + (bs+b2) ----
    bias_init(sbsc, qt, acc);
    #pragma unroll
    for (int k8 = 0; k8 < 8; k8++)
        mm_k8_l<false, SLS>(z0a + k8 * 32, slB + k8 * 32, acc);
    cp_wait<0>();
    __syncthreads();                               // W2 staged; Ws reads done

    {   // prefetch W3 -> slotB under the W2 mm
        const float* s3 = g_wc + GW_W3 + wrow * BW + wpart16;
        float* d3 = slotB + wrow * SLS + wpart16;
        #pragma unroll
        for (int j = 0; j < 4; j++) cp16(d3 + 4 * j, s3 + 4 * j);
        cp_commit();
    }

    // ---- residual B: acc += z1 @ W2 ; z2 = elu(acc) -> Z0 (own rows) ----
    #pragma unroll
    for (int k8 = 0; k8 < 8; k8++)
        mm_k8_l<false, SLS>(z1a + k8 * 32, slA + k8 * 32, acc);
    z_store<true>(sZ0, acc, wm, qid, qt);
    cp_wait<0>();
    __syncthreads();                               // W3 staged + visible

    // ---- layer 3: z3 = elu(z2 @ W3 + b3) -> Z1 (fp32 out, feeds head) ----
    bias_init(sb3, qt, acc);
    #pragma unroll
    for (int k8 = 0; k8 < 8; k8++)
        mm_k8_l<false, SLS>(z0a + k8 * 32, slB + k8 * 32, acc);
    z_store<false>(sZ1, acc, wm, qid, qt);
    __syncthreads();                               // head reads cross-warp

    // ---- head: threads 0..127, one triplet each (fp32) ----
    if (tid < TILE) {
        int t = t0 + tid;
        if (t < nT) {
            const float* zrow = sZ1 + tid * ZS;
            float c0 = sb4[0], c1 = sb4[1];
            #pragma unroll
            for (int k4 = 0; k4 < 16; k4++) {
                float4 z4 = *(const float4*)(zrow + k4 * 4);
                float4 wA = *(const float4*)(sW4 + k4 * 8);
                float4 wB = *(const float4*)(sW4 + k4 * 8 + 4);
                c0 += z4.x * wA.x + z4.y * wA.z + z4.z * wB.x + z4.w * wB.z;
                c1 += z4.x * wA.y + z4.y * wA.w + z4.z * wB.y + z4.w * wB.w;
            }
            float eq = PI_F / (1.0f + expf(-c0 * (EQ_STD / PI_F)));
            float kk = K_STD * eluf(c1 + K_MEAN / K_STD);
            *(float2*)(out + (size_t)t * 2) = make_float2(eq, kk);
        }
    }
}

} // namespace

extern "C" void kernel_launch(void* const* d_in, const int* in_sizes, int n_in,
                              void* d_out, int out_size) {
    const float* h   = (const float*)d_in[0];
    const int*   idx = (const int*)  d_in[1];
    const float* W0  = (const float*)d_in[2];
    const float* b0  = (const float*)d_in[3];
    const float* Ws  = (const float*)d_in[4];
    const float* bs  = (const float*)d_in[5];
    const float* W1  = (const float*)d_in[6];
    const float* b1  = (const float*)d_in[7];
    const float* W2  = (const float*)d_in[8];
    const float* b2  = (const float*)d_in[9];
    const float* W3  = (const float*)d_in[10];
    const float* b3  = (const float*)d_in[11];
    const float* W4  = (const float*)d_in[12];
    const float* b4  = (const float*)d_in[13];
    float* out = (float*)d_out;

    int nT = in_sizes[1] / 3;
    int grid = (nT + TILE - 1) / TILE;

    wcvt_kernel<<<(GW_TOTAL + 255) / 256, 256>>>(W0, W1, Ws, W2, W3);

    cudaFuncSetAttribute(wap_kernel,
                         cudaFuncAttributeMaxDynamicSharedMemorySize,
                         (int)SMEM_BYTES);
    wap_kernel<<<grid, NTHREADS, SMEM_BYTES>>>(
        h, idx, b0, bs, b1, b2, b3, W4, b4, out, nT);
    (void)n_in; (void)out_size;
}

// round 17
// speedup vs baseline: 2.7545x; 1.2704x over previous
#include <cuda_runtime.h>
#include <math.h>

// ---------------------------------------------------------------------------
// WriteAngleParameters, 3-kernel pipeline:
//   1) wcvt:  weights -> tf32, n-major (W0 re-laid as P-projection [192][256])
//   2) pc:    P[n, s*64+j] = h[n,:] @ W0[s*256:(s+1)*256, j]  (+b0 folded, s=0)
//             dense [200K,256]x[256,192] tf32 GEMM -> g_C scratch
//   3) main:  z0 = elu(P0[i0]+P1[i1]+P2[i2]); 4 small 64x64 tf32 mma layers;
//             head transforms. TILE=128, 256 thr = 8 warps x 16 rows.
// ---------------------------------------------------------------------------

namespace {

constexpr int REP      = 256;
constexpr int BW       = 64;
constexpr int TILE     = 128;
constexpr int NTHREADS = 256;
constexpr int SLS      = 68;     // slot n-row stride (floats)
constexpr int ZS       = 68;     // z row stride (floats)

constexpr float PI_F   = 3.14159265358979323846f;
constexpr float EQ_STD = 0.1f;
constexpr float K_MEAN = 120.0f;
constexpr float K_STD  = 50.0f;

// ---- main-kernel smem (floats) ----
constexpr int OFF_Z0   = 0;                       // 128*68
constexpr int OFF_Z1   = 8704;
constexpr int OFF_SL   = 17408;                   // slotA; slotB at +SLSZ
constexpr int SLSZ     = BW * SLS;                // 4352
constexpr int OFF_W4   = OFF_SL + 2 * SLSZ;       // 26112 (128)
constexpr int OFF_B1   = OFF_W4 + 128;
constexpr int OFF_BSC  = OFF_B1 + 64;             // bs + b2
constexpr int OFF_B3   = OFF_BSC + 64;
constexpr int OFF_B4   = OFF_B3 + 64;             // 4
constexpr int SMEM_FLOATS = OFF_B4 + 4;
constexpr size_t SMEM_BYTES = (size_t)SMEM_FLOATS * sizeof(float);  // ~106 KB

// ---- precompute-kernel smem ----
constexpr int PC_AS   = 36;                       // A stage row stride
constexpr int PC_BS   = 36;                       // B stage n-row stride
constexpr int PCA_SZ  = 128 * PC_AS;              // 4608
constexpr int PCB_OFF = 2 * PCA_SZ;               // 9216
constexpr int PCB_SZ  = 96 * PC_BS;               // 3456
constexpr int PC_SMEM_FLOATS = PCB_OFF + 2 * PCB_SZ;   // 16128
constexpr size_t PC_SMEM_BYTES = (size_t)PC_SMEM_FLOATS * sizeof(float);

// tf32 weights: W0 as P-projection n-major [192][256] | W1|Ws|W2|W3 n-major [64][64]
constexpr int GW_W0 = 0;
constexpr int GW_W1 = 49152;
constexpr int GW_WS = 53248;
constexpr int GW_W2 = 57344;
constexpr int GW_W3 = 61440;
constexpr int GW_TOTAL = 65536;

constexpr int MAX_NODES = 200064;                 // 200000 ceil to 128

__device__ float g_wc[GW_TOTAL];
__device__ float g_C[(size_t)MAX_NODES * 192];    // P table scratch (~154 MB)

__device__ __forceinline__ unsigned cvt_tf32(float f) {
    unsigned u;
    asm("cvt.rna.tf32.f32 %0, %1;" : "=r"(u) : "f"(f));
    return u;
}

__device__ __forceinline__ void hmma(float* d, unsigned a0, unsigned a1,
                                     unsigned a2, unsigned a3,
                                     unsigned b0, unsigned b1) {
    asm("mma.sync.aligned.m16n8k8.row.col.f32.tf32.tf32.f32 "
        "{%0,%1,%2,%3}, {%4,%5,%6,%7}, {%8,%9}, {%0,%1,%2,%3};"
        : "+f"(d[0]), "+f"(d[1]), "+f"(d[2]), "+f"(d[3])
        : "r"(a0), "r"(a1), "r"(a2), "r"(a3), "r"(b0), "r"(b1));
}

__device__ __forceinline__ void ldsm4(unsigned& r0, unsigned& r1,
                                      unsigned& r2, unsigned& r3, unsigned addr) {
    asm volatile("ldmatrix.sync.aligned.m8n8.x4.shared.b16 {%0,%1,%2,%3}, [%4];"
                 : "=r"(r0), "=r"(r1), "=r"(r2), "=r"(r3) : "r"(addr));
}

__device__ __forceinline__ void cp16(float* dst_smem, const float* src) {
    unsigned sdst = (unsigned)__cvta_generic_to_shared(dst_smem);
    asm volatile("cp.async.cg.shared.global [%0], [%1], 16;" :: "r"(sdst), "l"(src));
}
__device__ __forceinline__ void cp_commit() {
    asm volatile("cp.async.commit_group;" ::: "memory");
}
template<int N>
__device__ __forceinline__ void cp_wait() {
    asm volatile("cp.async.wait_group %0;" :: "n"(N) : "memory");
}

__device__ __forceinline__ float eluf(float x) {
    return x > 0.0f ? x : expm1f(x);
}

// 8 n-tiles (small layers): 1 A-ldsm + 4 B-ldsm + 8 hmma
__device__ __forceinline__ void mm_k8_l(unsigned a_addr, unsigned b_addr,
                                        float acc[8][4]) {
    unsigned a0, a1, a2, a3;
    ldsm4(a0, a1, a2, a3, a_addr);
    #pragma unroll
    for (int t = 0; t < 4; t++) {
        unsigned b0, b1, b2, b3;
        ldsm4(b0, b1, b2, b3, b_addr + t * (16 * SLS * 4));
        hmma(acc[2 * t],     a0, a1, a2, a3, b0, b1);
        hmma(acc[2 * t + 1], a0, a1, a2, a3, b2, b3);
    }
}

// 12 n-tiles (precompute): A needs tf32 cvt (h is fp32)
__device__ __forceinline__ void mm_k8_pc(unsigned a_addr, unsigned b_addr,
                                         float acc[12][4]) {
    unsigned a0, a1, a2, a3;
    ldsm4(a0, a1, a2, a3, a_addr);
    a0 = cvt_tf32(__uint_as_float(a0));
    a1 = cvt_tf32(__uint_as_float(a1));
    a2 = cvt_tf32(__uint_as_float(a2));
    a3 = cvt_tf32(__uint_as_float(a3));
    #pragma unroll
    for (int t = 0; t < 6; t++) {
        unsigned b0, b1, b2, b3;
        ldsm4(b0, b1, b2, b3, b_addr + t * (16 * PC_BS * 4));
        hmma(acc[2 * t],     a0, a1, a2, a3, b0, b1);
        hmma(acc[2 * t + 1], a0, a1, a2, a3, b2, b3);
    }
}

__device__ __forceinline__ void bias_init(const float* sb, int qt, float acc[8][4]) {
    #pragma unroll
    for (int t = 0; t < 8; t++) {
        float2 b = *(const float2*)(sb + t * 8 + qt * 2);
        acc[t][0] = b.x; acc[t][1] = b.y; acc[t][2] = b.x; acc[t][3] = b.y;
    }
}

template<bool CVT>
__device__ __forceinline__ void z_store(float* z, const float acc[8][4],
                                        int wm, int qid, int qt) {
    int r0 = wm + qid;
    #pragma unroll
    for (int t = 0; t < 8; t++) {
        float2 lo = make_float2(eluf(acc[t][0]), eluf(acc[t][1]));
        float2 hi = make_float2(eluf(acc[t][2]), eluf(acc[t][3]));
        if (CVT) {
            lo.x = __uint_as_float(cvt_tf32(lo.x));
            lo.y = __uint_as_float(cvt_tf32(lo.y));
            hi.x = __uint_as_float(cvt_tf32(hi.x));
            hi.y = __uint_as_float(cvt_tf32(hi.y));
        }
        int c = t * 8 + qt * 2;
        *(float2*)(z + r0 * ZS + c)       = lo;
        *(float2*)(z + (r0 + 8) * ZS + c) = hi;
    }
}

// -------- kernel 1: weight tf32 conversion + relayout --------
__global__ void wcvt_kernel(const float* __restrict__ W0, const float* __restrict__ W1,
                            const float* __restrict__ Ws, const float* __restrict__ W2,
                            const float* __restrict__ W3) {
    int i = blockIdx.x * 256 + threadIdx.x;
    if (i >= GW_TOTAL) return;
    float v;
    if (i < GW_W1) {                       // W0 -> [sj][k256], sj = s*64+j
        int sj = i >> 8, k = i & 255;
        int s = sj >> 6, j = sj & 63;
        v = W0[(s * 256 + k) * 64 + j];
    } else {                               // small: n-major [n][k]
        int j2 = i - GW_W1;
        int m = j2 >> 12;                  // 0..3 -> W1, Ws, W2, W3
        int n = (j2 & 4095) >> 6, k = j2 & 63;
        const float* src = m == 0 ? W1 : m == 1 ? Ws : m == 2 ? W2 : W3;
        v = src[k * 64 + n];
    }
    g_wc[i] = __uint_as_float(cvt_tf32(v));
}

// -------- kernel 2: P-table precompute GEMM --------
// grid (ceil(nNodes/128), 2); CTA computes 128 rows x 96 cols (sj0 = y*96).
// 8 warps x 16 rows, each warp all 96 cols. K=256 in 8 chunks of 32, depth-2.
__global__ void __launch_bounds__(256, 2)
pc_kernel(const float* __restrict__ h, const float* __restrict__ b0, int nNodes)
{
    extern __shared__ float smem[];
    const int tid  = threadIdx.x;
    const int lane = tid & 31;
    const int qid  = lane >> 2;
    const int qt   = lane & 3;
    const int wm   = (tid >> 5) * 16;
    const int sj0  = blockIdx.y * 96;

    const unsigned smem_u32 = (unsigned)__cvta_generic_to_shared(smem);
    const unsigned a_off = (unsigned)(((wm + (lane & 15)) * PC_AS + ((lane >> 4) & 1) * 4) * 4);
    const unsigned b_off = (unsigned)((((lane & 7) + ((lane >> 4) & 1) * 8) * PC_BS
                                      + ((lane >> 3) & 1) * 4) * 4);

    // staging roles
    const int arow  = tid >> 1;            // 0..127
    const int apart = (tid & 1) * 16;
    int agrow = blockIdx.x * 128 + arow;
    if (agrow >= nNodes) agrow = nNodes - 1;
    const float* asrc = h + (size_t)agrow * REP;
    const int brow  = tid >> 1;            // 0..95 for tid < 192
    const int bpart = (tid & 1) * 16;

    float acc[12][4];
    #pragma unroll
    for (int t = 0; t < 12; t++)
        acc[t][0] = acc[t][1] = acc[t][2] = acc[t][3] = 0.0f;

    // stage 0
    {
        const float* xs = asrc + 0 * 32 + apart;
        float* xd = smem + 0 * PCA_SZ + arow * PC_AS + apart;
        #pragma unroll
        for (int j = 0; j < 4; j++) cp16(xd + 4 * j, xs + 4 * j);
        if (tid < 192) {
            const float* ws = g_wc + GW_W0 + (size_t)(sj0 + brow) * 256 + 0 * 32 + bpart;
            float* wd = smem + PCB_OFF + 0 * PCB_SZ + brow * PC_BS + bpart;
            #pragma unroll
            for (int j = 0; j < 4; j++) cp16(wd + 4 * j, ws + 4 * j);
        }
        cp_commit();
    }

    for (int s = 0; s < 8; s++) {
        __syncthreads();                   // compute(s-1) done; buffer (s+1)&1 free
        if (s + 1 < 8) {
            const int s2 = s + 1;
            const float* xs = asrc + s2 * 32 + apart;
            float* xd = smem + (s2 & 1) * PCA_SZ + arow * PC_AS + apart;
            #pragma unroll
            for (int j = 0; j < 4; j++) cp16(xd + 4 * j, xs + 4 * j);
            if (tid < 192) {
                const float* ws = g_wc + GW_W0 + (size_t)(sj0 + brow) * 256 + s2 * 32 + bpart;
                float* wd = smem + PCB_OFF + (s2 & 1) * PCB_SZ + brow * PC_BS + bpart;
                #pragma unroll
                for (int j = 0; j < 4; j++) cp16(wd + 4 * j, ws + 4 * j);
            }
            cp_commit();
            cp_wait<1>();
        } else {
            cp_wait<0>();
        }
        __syncthreads();                   // stage s visible
        unsigned xa = smem_u32 + (unsigned)(((s & 1) * PCA_SZ) * 4) + a_off;
        unsigned ba = smem_u32 + (unsigned)((PCB_OFF + (s & 1) * PCB_SZ) * 4) + b_off;
        #pragma unroll
        for (int k8 = 0; k8 < 4; k8++)
            mm_k8_pc(xa + k8 * 32, ba + k8 * 32, acc);
    }

    // store (+ b0 folded into slot 0 columns)
    const int r0 = blockIdx.x * 128 + wm + qid;
    #pragma unroll
    for (int tt = 0; tt < 12; tt++) {
        int sj = sj0 + tt * 8 + qt * 2;
        float2 v0 = make_float2(acc[tt][0], acc[tt][1]);
        float2 v1 = make_float2(acc[tt][2], acc[tt][3]);
        if (sj < 64) {
            float a0 = b0[sj], a1 = b0[sj + 1];
            v0.x += a0; v0.y += a1; v1.x += a0; v1.y += a1;
        }
        if (r0 < nNodes)     *(float2*)(g_C + (size_t)r0 * 192 + sj) = v0;
        if (r0 + 8 < nNodes) *(float2*)(g_C + (size_t)(r0 + 8) * 192 + sj) = v1;
    }
}

// -------- kernel 3: main (gather-sum z0 + small layers + head) --------
__global__ void __launch_bounds__(NTHREADS, 2)
wap_kernel(const int* __restrict__ idxs,
           const float* __restrict__ bs, const float* __restrict__ b1,
           const float* __restrict__ b2, const float* __restrict__ b3,
           const float* __restrict__ W4, const float* __restrict__ b4,
           float* __restrict__ out, int nT)
{
    extern __shared__ float smem[];
    float* sZ0   = smem + OFF_Z0;
    float* sZ1   = smem + OFF_Z1;
    float* slotA = smem + OFF_SL;
    float* slotB = smem + OFF_SL + SLSZ;
    float* sW4   = smem + OFF_W4;
    float* sb1   = smem + OFF_B1;
    float* sbsc  = smem + OFF_BSC;
    float* sb3   = smem + OFF_B3;
    float* sb4   = smem + OFF_B4;

    const int tid  = threadIdx.x;
    const int lane = tid & 31;
    const int qid  = lane >> 2;
    const int qt   = lane & 3;
    const int wm   = (tid >> 5) * 16;
    const int t0   = blockIdx.x * TILE;

    const unsigned smem_u32 = (unsigned)__cvta_generic_to_shared(smem);
    const unsigned a_offZ = (unsigned)(((wm + (lane & 15)) * ZS + ((lane >> 4) & 1) * 4) * 4);
    const unsigned b_offS = (unsigned)((((lane & 7) + ((lane >> 4) & 1) * 8) * SLS
                                       + ((lane >> 3) & 1) * 4) * 4);

    // slot staging roles
    const int wrow    = tid >> 2;          // 0..63
    const int wpart16 = (tid & 3) * 16;

    // ---- stage W1 -> slotA, Ws -> slotB (overlapped with gather) ----
    {
        const float* s1 = g_wc + GW_W1 + wrow * BW + wpart16;
        const float* s2 = g_wc + GW_WS + wrow * BW + wpart16;
        float* d1 = slotA + wrow * SLS + wpart16;
        float* d2 = slotB + wrow * SLS + wpart16;
        #pragma unroll
        for (int j = 0; j < 4; j++) { cp16(d1 + 4 * j, s1 + 4 * j); cp16(d2 + 4 * j, s2 + 4 * j); }
        cp_commit();
    }

    // ---- biases / W4 ----
    if (tid < 128) sW4[tid] = W4[tid];
    if (tid < 64) {
        sb1[tid] = b1[tid];
        sbsc[tid] = bs[tid] + b2[tid];
        sb3[tid] = b3[tid];
    }
    if (tid < 2) sb4[tid] = b4[tid];

    // ---- gather-sum z0: z0 = elu(P0[i0] + P1[i1] + P2[i2]) (b0 pre-folded) ----
    {
        const int row  = tid >> 1;
        const int half = (tid & 1) * 32;
        int t_my = t0 + row;
        if (t_my >= nT) t_my = nT - 1;     // clamp tail (extras computed, not stored)
        const float* p0 = g_C + (size_t)idxs[3 * t_my + 0] * 192 +   0 + half;
        const float* p1 = g_C + (size_t)idxs[3 * t_my + 1] * 192 +  64 + half;
        const float* p2 = g_C + (size_t)idxs[3 * t_my + 2] * 192 + 128 + half;
        float* zd = sZ0 + row * ZS + half;
        #pragma unroll
        for (int j = 0; j < 8; j++) {
            float4 a = *(const float4*)(p0 + 4 * j);
            float4 b = *(const float4*)(p1 + 4 * j);
            float4 c = *(const float4*)(p2 + 4 * j);
            float4 v;
            v.x = __uint_as_float(cvt_tf32(eluf(a.x + b.x + c.x)));
            v.y = __uint_as_float(cvt_tf32(eluf(a.y + b.y + c.y)));
            v.z = __uint_as_float(cvt_tf32(eluf(a.z + b.z + c.z)));
            v.w = __uint_as_float(cvt_tf32(eluf(a.w + b.w + c.w)));
            *(float4*)(zd + 4 * j) = v;
        }
    }
    cp_wait<0>();
    __syncthreads();                       // z0 + W1 + Ws visible

    const unsigned z0a = smem_u32 + (unsigned)(OFF_Z0 * 4) + a_offZ;
    const unsigned z1a = smem_u32 + (unsigned)(OFF_Z1 * 4) + a_offZ;
    const unsigned slA = smem_u32 + (unsigned)(OFF_SL * 4) + b_offS;
    const unsigned slB = slA + (unsigned)(SLSZ * 4);

    float acc[8][4];

    // ---- layer 1: z1 = elu(z0 @ W1 + b1) -> Z1 ----
    bias_init(sb1, qt, acc);
    #pragma unroll
    for (int k8 = 0; k8 < 8; k8++)
        mm_k8_l(z0a + k8 * 32, slA + k8 * 32, acc);
    z_store<true>(sZ1, acc, wm, qid, qt);
    __syncthreads();                       // W1 reads done -> slotA reusable

    {   // prefetch W2 -> slotA under the Ws mm
        const float* s2 = g_wc + GW_W2 + wrow * BW + wpart16;
        float* d2 = slotA + wrow * SLS + wpart16;
        #pragma unroll
        for (int j = 0; j < 4; j++) cp16(d2 + 4 * j, s2 + 4 * j);
        cp_commit();
    }

    // ---- residual A: acc = z0 @ Ws + (bs+b2) ----
    bias_init(sbsc, qt, acc);
    #pragma unroll
    for (int k8 = 0; k8 < 8; k8++)
        mm_k8_l(z0a + k8 * 32, slB + k8 * 32, acc);
    cp_wait<0>();
    __syncthreads();                       // W2 staged; Ws reads done

    {   // prefetch W3 -> slotB under the W2 mm
        const float* s3 = g_wc + GW_W3 + wrow * BW + wpart16;
        float* d3 = slotB + wrow * SLS + wpart16;
        #pragma unroll
        for (int j = 0; j < 4; j++) cp16(d3 + 4 * j, s3 + 4 * j);
        cp_commit();
    }

    // ---- residual B: acc += z1 @ W2 ; z2 = elu(acc) -> Z0 (own rows) ----
    #pragma unroll
    for (int k8 = 0; k8 < 8; k8++)
        mm_k8_l(z1a + k8 * 32, slA + k8 * 32, acc);
    z_store<true>(sZ0, acc, wm, qid, qt);
    cp_wait<0>();
    __syncthreads();                       // W3 staged + visible

    // ---- layer 3: z3 = elu(z2 @ W3 + b3) -> Z1 (fp32, feeds head) ----
    bias_init(sb3, qt, acc);
    #pragma unroll
    for (int k8 = 0; k8 < 8; k8++)
        mm_k8_l(z0a + k8 * 32, slB + k8 * 32, acc);
    z_store<false>(sZ1, acc, wm, qid, qt);
    __syncthreads();                       // head reads cross-warp

    // ---- head: threads 0..127, one triplet each (fp32) ----
    if (tid < TILE) {
        int t = t0 + tid;
        if (t < nT) {
            const float* zrow = sZ1 + tid * ZS;
            float c0 = sb4[0], c1 = sb4[1];
            #pragma unroll
            for (int k4 = 0; k4 < 16; k4++) {
                float4 z4 = *(const float4*)(zrow + k4 * 4);
                float4 wA = *(const float4*)(sW4 + k4 * 8);
                float4 wB = *(const float4*)(sW4 + k4 * 8 + 4);
                c0 += z4.x * wA.x + z4.y * wA.z + z4.z * wB.x + z4.w * wB.z;
                c1 += z4.x * wA.y + z4.y * wA.w + z4.z * wB.y + z4.w * wB.w;
            }
            float eq = PI_F / (1.0f + expf(-c0 * (EQ_STD / PI_F)));
            float kk = K_STD * eluf(c1 + K_MEAN / K_STD);
            *(float2*)(out + (size_t)t * 2) = make_float2(eq, kk);
        }
    }
}

} // namespace

extern "C" void kernel_launch(void* const* d_in, const int* in_sizes, int n_in,
                              void* d_out, int out_size) {
    const float* h   = (const float*)d_in[0];
    const int*   idx = (const int*)  d_in[1];
    const float* W0  = (const float*)d_in[2];
    const float* b0  = (const float*)d_in[3];
    const float* Ws  = (const float*)d_in[4];
    const float* bs  = (const float*)d_in[5];
    const float* W1  = (const float*)d_in[6];
    const float* b1  = (const float*)d_in[7];
    const float* W2  = (const float*)d_in[8];
    const float* b2  = (const float*)d_in[9];
    const float* W3  = (const float*)d_in[10];
    const float* b3  = (const float*)d_in[11];
    const float* W4  = (const float*)d_in[12];
    const float* b4  = (const float*)d_in[13];
    float* out = (float*)d_out;

    int nNodes = in_sizes[0] / REP;
    int nT = in_sizes[1] / 3;

    wcvt_kernel<<<(GW_TOTAL + 255) / 256, 256>>>(W0, W1, Ws, W2, W3);

    cudaFuncSetAttribute(pc_kernel,
                         cudaFuncAttributeMaxDynamicSharedMemorySize,
                         (int)PC_SMEM_BYTES);
    dim3 pcg((nNodes + 127) / 128, 2);
    pc_kernel<<<pcg, 256, PC_SMEM_BYTES>>>(h, b0, nNodes);

    cudaFuncSetAttribute(wap_kernel,
                         cudaFuncAttributeMaxDynamicSharedMemorySize,
                         (int)SMEM_BYTES);
    int grid = (nT + TILE - 1) / TILE;
    wap_kernel<<<grid, NTHREADS, SMEM_BYTES>>>(
        idx, bs, b1, b2, b3, W4, b4, out, nT);
    (void)n_in; (void)out_size;
}